// round 12
// baseline (speedup 1.0000x reference)
#include <cuda_runtime.h>
#include <cuda_bf16.h>
#include <math.h>
#include <stdint.h>

// ---------------- problem constants ----------------
#define BB   2
#define SS   2048
#define HH   1024
#define NHH  16
#define DHH  64
#define FFD  4096
#define MM   (BB*SS)     // 4096 rows

// ---------------- scratch (static device globals; no allocation) -----------
__device__ float          g_x  [(size_t)MM * HH];      // running residual (fp32)
__device__ __nv_bfloat16  g_h  [(size_t)MM * HH];      // layernorm output
__device__ __nv_bfloat16  g_qkv[(size_t)MM * 3 * HH];  // qkv projection
__device__ __nv_bfloat16  g_ctx[(size_t)MM * HH];      // attention context
__device__ __nv_bfloat16  g_ff [(size_t)MM * FFD];     // mlp hidden
__device__ __nv_bfloat16  g_wr [(size_t)25165824];     // bf16 weights (all)

// ---------------- small helpers ----------------
__device__ __forceinline__ float warp_sum(float v) {
#pragma unroll
    for (int o = 16; o; o >>= 1) v += __shfl_xor_sync(0xffffffffu, v, o);
    return v;
}
__device__ __forceinline__ float gelu_exact(float v) {
    return 0.5f * v * (1.0f + erff(v * 0.70710678118654752f));
}
#define MMA_BF16(d, a0, a1, a2, a3, b0, b1)                                   \
    asm volatile("mma.sync.aligned.m16n8k16.row.col.f32.bf16.bf16.f32 "       \
                 "{%0,%1,%2,%3}, {%4,%5,%6,%7}, {%8,%9}, {%0,%1,%2,%3};"      \
                 : "+f"((d)[0]), "+f"((d)[1]), "+f"((d)[2]), "+f"((d)[3])     \
                 : "r"(a0), "r"(a1), "r"(a2), "r"(a3), "r"(b0), "r"(b1))

__device__ __forceinline__ void ldsm_x4(uint32_t* r, uint32_t a) {
    asm volatile("ldmatrix.sync.aligned.m8n8.x4.shared.b16 {%0,%1,%2,%3}, [%4];"
                 : "=r"(r[0]), "=r"(r[1]), "=r"(r[2]), "=r"(r[3]) : "r"(a));
}
__device__ __forceinline__ void ldsm_x4t(uint32_t* r, uint32_t a) {
    asm volatile("ldmatrix.sync.aligned.m8n8.x4.trans.shared.b16 {%0,%1,%2,%3}, [%4];"
                 : "=r"(r[0]), "=r"(r[1]), "=r"(r[2]), "=r"(r[3]) : "r"(a));
}
#define CP16(dst, src)                                                         \
    asm volatile("cp.async.cg.shared.global [%0], [%1], 16;\n" :: "r"(dst), "l"(src))
#define CP_COMMIT() asm volatile("cp.async.commit_group;\n")
#define CP_WAIT0()  asm volatile("cp.async.wait_group 0;\n")
#define CP_WAIT1()  asm volatile("cp.async.wait_group 1;\n")

// ---------------- copy input -> g_x ----------------
__global__ void copy_kernel(const float* __restrict__ in, float* __restrict__ out, int n4) {
    int i = blockIdx.x * blockDim.x + threadIdx.x;
    if (i < n4) ((float4*)out)[i] = ((const float4*)in)[i];
}

// ---------------- fp32 -> bf16 weight conversion ----------------
__global__ void cvt_kernel(const float* __restrict__ in, __nv_bfloat16* __restrict__ out, int n4) {
    int i = blockIdx.x * blockDim.x + threadIdx.x;
    if (i < n4) {
        const float4 v = ((const float4*)in)[i];
        __nv_bfloat162 a = __floats2bfloat162_rn(v.x, v.y);
        __nv_bfloat162 b = __floats2bfloat162_rn(v.z, v.w);
        uint2 w; w.x = *(uint32_t*)&a; w.y = *(uint32_t*)&b;
        ((uint2*)out)[i] = w;
    }
}

// ---------------- layernorm: 1 block (256 thr) per row of 1024 -------------
__global__ void ln_kernel(const float* __restrict__ x, const float* __restrict__ w,
                          const float* __restrict__ b, __nv_bfloat16* __restrict__ o) {
    __shared__ float r1[8], r2[8];
    const int row = blockIdx.x, tid = threadIdx.x;
    const float4 v = *(const float4*)(x + (size_t)row * HH + tid * 4);
    float s = v.x + v.y + v.z + v.w;
    s = warp_sum(s);
    if ((tid & 31) == 0) r1[tid >> 5] = s;
    __syncthreads();
    float mean = 0.f;
#pragma unroll
    for (int i = 0; i < 8; i++) mean += r1[i];
    mean *= (1.f / (float)HH);
    const float d0 = v.x - mean, d1 = v.y - mean, d2 = v.z - mean, d3 = v.w - mean;
    float sq = d0 * d0 + d1 * d1 + d2 * d2 + d3 * d3;
    sq = warp_sum(sq);
    if ((tid & 31) == 0) r2[tid >> 5] = sq;
    __syncthreads();
    float var = 0.f;
#pragma unroll
    for (int i = 0; i < 8; i++) var += r2[i];
    var *= (1.f / (float)HH);
    const float rstd = rsqrtf(var + 1e-5f);
    const float4 wv = *(const float4*)(w + tid * 4);
    const float4 bv = *(const float4*)(b + tid * 4);
    __nv_bfloat162 o0 = __floats2bfloat162_rn(d0 * rstd * wv.x + bv.x, d1 * rstd * wv.y + bv.y);
    __nv_bfloat162 o1 = __floats2bfloat162_rn(d2 * rstd * wv.z + bv.z, d3 * rstd * wv.w + bv.w);
    uint2 pk; pk.x = *(uint32_t*)&o0; pk.y = *(uint32_t*)&o1;
    *(uint2*)(o + (size_t)row * HH + tid * 4) = pk;
}

// ---------------- bf16 tensor-core GEMM (TN) -------------------------------
// CTA tile 128x256x64, 8 warps (2x4), warp tile 64x64, 3-stage cp.async,
// swizzled ldmatrix. Rows = 64 bf16 = 128B = 8 chunks; chunk' = chunk^(row&7).
#define GST    49152                 // bytes per stage (A 16KB + B 32KB)
#define GSMEM  (3*GST)               // 147456

template <int EPI>
__global__ void __launch_bounds__(256, 1) mma_tn(
        const __nv_bfloat16* __restrict__ A, const __nv_bfloat16* __restrict__ W,
        const float* __restrict__ bias, const float* __restrict__ res,
        void* __restrict__ Cout, int M, int N, int K) {
    extern __shared__ uint8_t smraw[];
    const uint32_t smbase = (uint32_t)__cvta_generic_to_shared(smraw);
    const int tid = threadIdx.x;
    const int warp = tid >> 5, lane = tid & 31;
    const int wm = warp >> 2, wn = warp & 3;      // 2 x 4 warp grid
    const int g = lane >> 2, t = lane & 3;
    const int mb = blockIdx.y << 7, nb = blockIdx.x << 8;

    // ---- staging geometry ----
    const int ra = tid >> 1, kca = (tid & 1) << 2;     // A: row, chunks kca..+3
    const __nv_bfloat16* Ag = A + (size_t)(mb + ra) * K + kca * 8;
    const __nv_bfloat16* Wg = W + (size_t)(nb + tid) * K;   // B: row tid, 8 chunks
    uint32_t offA[4], offB[8];
#pragma unroll
    for (int i = 0; i < 4; i++)
        offA[i] = ra * 128 + (((kca + i) ^ (ra & 7)) << 4);
#pragma unroll
    for (int i = 0; i < 8; i++)
        offB[i] = 16384 + tid * 128 + ((i ^ (tid & 7)) << 4);

    // ---- fragment addresses ----
    const uint32_t la7 = lane & 7, la15 = lane & 15;
    const uint32_t hiA = lane >> 4, hiB = (lane >> 3) & 1;
    const uint32_t aRow = (wm * 64 + la15) * 128;
    const uint32_t bRow = (wn * 64 + la7 + ((lane >> 4) << 3)) * 128;

    float acc[4][8][4];
#pragma unroll
    for (int a = 0; a < 4; a++)
#pragma unroll
        for (int b = 0; b < 8; b++)
#pragma unroll
            for (int c = 0; c < 4; c++) acc[a][b][c] = 0.f;

    const int nk = K >> 6;
    auto issue = [&](int kt, int s) {
        const __nv_bfloat16* ap = Ag + (kt << 6);
        const __nv_bfloat16* wp = Wg + (kt << 6);
        const uint32_t sb = smbase + (uint32_t)s * GST;
#pragma unroll
        for (int i = 0; i < 4; i++) CP16(sb + offA[i], ap + i * 8);
#pragma unroll
        for (int i = 0; i < 8; i++) CP16(sb + offB[i], wp + i * 8);
        CP_COMMIT();
    };

    issue(0, 0);
    issue(1, 1);

    int stage = 0;
    for (int kt = 0; kt < nk; ++kt) {
        if (kt == nk - 1) CP_WAIT0(); else CP_WAIT1();
        __syncthreads();
        if (kt + 2 < nk) {
            int ns = stage + 2; if (ns >= 3) ns -= 3;
            issue(kt + 2, ns);
        }
        const uint32_t sA = smbase + (uint32_t)stage * GST;
        const uint32_t sW = sA + 16384;
#pragma unroll
        for (int kk = 0; kk < 4; kk++) {
            const uint32_t swzA = (((2 * kk + hiA) ^ la7) << 4);
            const uint32_t swzB = (((2 * kk + hiB) ^ la7) << 4);
            uint32_t af[4][4], bf[4][4];
#pragma unroll
            for (int mt = 0; mt < 4; mt++)
                ldsm_x4(af[mt], sA + aRow + mt * 2048 + swzA);
#pragma unroll
            for (int p = 0; p < 4; p++)
                ldsm_x4(bf[p], sW + bRow + p * 2048 + swzB);
#pragma unroll
            for (int mt = 0; mt < 4; mt++)
#pragma unroll
                for (int nt = 0; nt < 8; nt++)
                    MMA_BF16(acc[mt][nt], af[mt][0], af[mt][1], af[mt][2], af[mt][3],
                             bf[nt >> 1][(nt & 1) * 2], bf[nt >> 1][(nt & 1) * 2 + 1]);
        }
        if (++stage == 3) stage = 0;
    }

    // epilogue: c0,c1 -> (row g, cols 2t,2t+1); c2,c3 -> (row g+8)
#pragma unroll
    for (int mt = 0; mt < 4; mt++) {
        const int r0 = mb + wm * 64 + mt * 16 + g;
#pragma unroll
        for (int nt = 0; nt < 8; nt++) {
            const int cb = nb + wn * 64 + nt * 8 + 2 * t;
            const float b0 = bias[cb], b1 = bias[cb + 1];
#pragma unroll
            for (int hh = 0; hh < 2; hh++) {
                const int rr = r0 + hh * 8;
                float v0 = acc[mt][nt][2 * hh + 0] + b0;
                float v1 = acc[mt][nt][2 * hh + 1] + b1;
                const size_t off = (size_t)rr * N + cb;
                if (EPI == 2) {
                    const float2 rv = *(const float2*)(res + off);
                    *(float2*)((float*)Cout + off) = make_float2(v0 + rv.x, v1 + rv.y);
                } else {
                    if (EPI == 1) { v0 = gelu_exact(v0); v1 = gelu_exact(v1); }
                    __nv_bfloat162 h2 = __floats2bfloat162_rn(v0, v1);
                    *(uint32_t*)((__nv_bfloat16*)Cout + off) = *(uint32_t*)&h2;
                }
            }
        }
    }
}

// ---------------- bf16 tensor-core flash attention (causal, ALiBi) ---------
// grid: (S/128, NH, B), 256 thr (8 warps x 16 q-rows). P kept in registers.
// smem: Q 16KB | 3 stages x (K 8KB + V 8KB + alibi 256B)
#define FSTG 16640
#define FLASH_SMEM (16384 + 3*FSTG)
__global__ void __launch_bounds__(256, 2) flash_kernel(
        const __nv_bfloat16* __restrict__ qkv, const float* __restrict__ alibi,
        __nv_bfloat16* __restrict__ ctx) {
    extern __shared__ uint8_t smraw[];
    const uint32_t smbase = (uint32_t)__cvta_generic_to_shared(smraw);
    uint32_t* smw = (uint32_t*)smraw;

    const int qt = blockIdx.x, hh = blockIdx.y, bb = blockIdx.z;
    const int tid = threadIdx.x;
    const int warp = tid >> 5, lane = tid & 31;
    const int g = lane >> 2, t = lane & 3;
    const int qbase = qt << 7;

    const __nv_bfloat16* qg  = qkv + (size_t)bb * SS * (3 * HH) + hh * DHH;
    const __nv_bfloat16* kg  = qg + HH;
    const __nv_bfloat16* vg  = qg + 2 * HH;
    const float* alg = alibi + ((size_t)bb * NHH + hh) * SS;

    const int lrow = (tid & 127) >> 1, lkc = (tid & 1) << 2;
    const __nv_bfloat16* kvsrc = ((tid >= 128) ? vg : kg) + (size_t)lrow * (3 * HH) + lkc * 8;
    uint32_t offKV[4];
#pragma unroll
    for (int i = 0; i < 4; i++)
        offKV[i] = ((tid >= 128) ? 8192u : 0u) + lrow * 128 + (((lkc + i) ^ (lrow & 7)) << 4);

    auto issue = [&](int jt, int s) {
        const uint32_t sb = smbase + 16384 + (uint32_t)s * FSTG;
        const __nv_bfloat16* src = kvsrc + (size_t)(jt << 6) * (3 * HH);
#pragma unroll
        for (int i = 0; i < 4; i++) CP16(sb + offKV[i], src + i * 8);
        if (tid < 16) CP16(sb + 16384 + tid * 16, alg + (jt << 6) + tid * 4);
        CP_COMMIT();
    };

    for (int f = tid; f < 1024; f += 256) {
        const int r = f >> 3, c = f & 7;
        const uint4 q4 = *(const uint4*)(qg + (size_t)(qbase + r) * (3 * HH) + c * 8);
        *(uint4*)(smw + r * 32 + ((c ^ (r & 7)) << 2)) = q4;
    }
    const int njt = 2 * qt + 2;
    issue(0, 0);
    issue(1, 1);
    __syncthreads();

    const uint32_t la7 = lane & 7, la15 = lane & 15;
    const uint32_t hiA = lane >> 4, hiB = (lane >> 3) & 1;
    const uint32_t qAddr = smbase + (warp * 16 + la15) * 128;
    uint32_t qf[4][4];
#pragma unroll
    for (int kk = 0; kk < 4; kk++)
        ldsm_x4(qf[kk], qAddr + (((2 * kk + hiA) ^ la7) << 4));

    const uint32_t kRow = (la7 + ((lane >> 4) << 3)) * 128;
    const uint32_t vKey = (la7 + (hiB << 3)) * 128;

    float mx[2] = { -INFINITY, -INFINITY };
    float lsum[2] = { 0.f, 0.f };
    float acc[8][4];
#pragma unroll
    for (int nt = 0; nt < 8; nt++)
#pragma unroll
        for (int c = 0; c < 4; c++) acc[nt][c] = 0.f;

    int stage = 0;
    for (int jt = 0; jt < njt; ++jt) {
        const int kbase = jt << 6;
        if (jt == njt - 1) CP_WAIT0(); else CP_WAIT1();
        __syncthreads();
        if (jt + 2 < njt) {
            int ns = stage + 2; if (ns >= 3) ns -= 3;
            issue(jt + 2, ns);
        }
        const uint32_t sK = smbase + 16384 + (uint32_t)stage * FSTG;
        const uint32_t sV = sK + 8192;
        const float* alS = (const float*)(smraw + 16384 + (size_t)stage * FSTG + 16384);

        float s[8][4];
#pragma unroll
        for (int nt = 0; nt < 8; nt++)
#pragma unroll
            for (int c = 0; c < 4; c++) s[nt][c] = 0.f;
#pragma unroll
        for (int kk = 0; kk < 4; ++kk) {
            const uint32_t swzB = (((2 * kk + hiB) ^ la7) << 4);
            uint32_t kf[4][4];
#pragma unroll
            for (int p = 0; p < 4; p++)
                ldsm_x4(kf[p], sK + kRow + p * 2048 + swzB);
#pragma unroll
            for (int nt = 0; nt < 8; ++nt)
                MMA_BF16(s[nt], qf[kk][0], qf[kk][1], qf[kk][2], qf[kk][3],
                         kf[nt >> 1][(nt & 1) * 2], kf[nt >> 1][(nt & 1) * 2 + 1]);
        }

        const bool need_mask = (jt >= 2 * qt);
        uint32_t pr[8][2];
#pragma unroll
        for (int r = 0; r < 2; ++r) {
            const int qr = qbase + warp * 16 + g + r * 8;
            float rowmax = -INFINITY;
#pragma unroll
            for (int nt = 0; nt < 8; ++nt) {
#pragma unroll
                for (int c = 0; c < 2; ++c) {
                    const int col = nt * 8 + 2 * t + c;
                    float v = s[nt][r * 2 + c] * 0.125f + alS[col];
                    if (need_mask && (kbase + col > qr)) v = -1e30f;
                    s[nt][r * 2 + c] = v;
                    rowmax = fmaxf(rowmax, v);
                }
            }
            rowmax = fmaxf(rowmax, __shfl_xor_sync(0xffffffffu, rowmax, 1));
            rowmax = fmaxf(rowmax, __shfl_xor_sync(0xffffffffu, rowmax, 2));
            const float mn = fmaxf(mx[r], rowmax);
            const float corr = __expf(mx[r] - mn);
            mx[r] = mn;
            float rs = 0.f;
#pragma unroll
            for (int nt = 0; nt < 8; ++nt) {
                const float p0 = __expf(s[nt][r * 2 + 0] - mn);
                const float p1 = __expf(s[nt][r * 2 + 1] - mn);
                const __nv_bfloat162 h2 = __floats2bfloat162_rn(p0, p1);
                rs += __bfloat162float(h2.x) + __bfloat162float(h2.y);
                pr[nt][r] = *(const uint32_t*)&h2;
            }
            rs += __shfl_xor_sync(0xffffffffu, rs, 1);
            rs += __shfl_xor_sync(0xffffffffu, rs, 2);
            lsum[r] = lsum[r] * corr + rs;
#pragma unroll
            for (int nt = 0; nt < 8; ++nt) {
                acc[nt][r * 2 + 0] *= corr;
                acc[nt][r * 2 + 1] *= corr;
            }
        }

#pragma unroll
        for (int kk = 0; kk < 4; ++kk) {
            const uint32_t a0 = pr[2 * kk][0],     a1 = pr[2 * kk][1];
            const uint32_t a2 = pr[2 * kk + 1][0], a3 = pr[2 * kk + 1][1];
            const uint32_t vBase = sV + vKey + kk * 2048;
            uint32_t vf[4][4];
#pragma unroll
            for (int p = 0; p < 4; p++) {
                const uint32_t chunk = 2 * p + hiA;
                ldsm_x4t(vf[p], vBase + ((chunk ^ la7) << 4));
            }
#pragma unroll
            for (int nt = 0; nt < 8; ++nt)
                MMA_BF16(acc[nt], a0, a1, a2, a3,
                         vf[nt >> 1][(nt & 1) * 2], vf[nt >> 1][(nt & 1) * 2 + 1]);
        }
        if (++stage == 3) stage = 0;
    }

    const float inv0 = 1.f / lsum[0], inv1 = 1.f / lsum[1];
    const int r0 = qbase + warp * 16 + g;
    __nv_bfloat16* o0 = ctx + ((size_t)bb * SS + r0) * HH + hh * DHH;
    __nv_bfloat16* o1 = o0 + (size_t)8 * HH;
#pragma unroll
    for (int nt = 0; nt < 8; ++nt) {
        const int col = nt * 8 + 2 * t;
        __nv_bfloat162 w0 = __floats2bfloat162_rn(acc[nt][0] * inv0, acc[nt][1] * inv0);
        __nv_bfloat162 w1 = __floats2bfloat162_rn(acc[nt][2] * inv1, acc[nt][3] * inv1);
        *(uint32_t*)(o0 + col) = *(uint32_t*)&w0;
        *(uint32_t*)(o1 + col) = *(uint32_t*)&w1;
    }
}

// ---------------- driver ----------------
extern "C" void kernel_launch(void* const* d_in, const int* in_sizes, int n_in,
                              void* d_out, int out_size) {
    const float* hs    = (const float*)d_in[0];
    const float* alibi = (const float*)d_in[1];
    const float* qkvw  = (const float*)d_in[2];
    const float* qkvb  = (const float*)d_in[3];
    const float* dw    = (const float*)d_in[4];
    const float* db    = (const float*)d_in[5];
    const float* w1    = (const float*)d_in[6];
    const float* b1    = (const float*)d_in[7];
    const float* w2    = (const float*)d_in[8];
    const float* b2    = (const float*)d_in[9];
    const float* l1w   = (const float*)d_in[10];
    const float* l1b   = (const float*)d_in[11];
    const float* l2w   = (const float*)d_in[12];
    const float* l2b   = (const float*)d_in[13];
    float* out = (float*)d_out;

    float *x;
    __nv_bfloat16 *h, *qkv, *ctx, *ff, *wr;
    cudaGetSymbolAddress((void**)&x,   g_x);
    cudaGetSymbolAddress((void**)&h,   g_h);
    cudaGetSymbolAddress((void**)&qkv, g_qkv);
    cudaGetSymbolAddress((void**)&ctx, g_ctx);
    cudaGetSymbolAddress((void**)&ff,  g_ff);
    cudaGetSymbolAddress((void**)&wr,  g_wr);

    cudaFuncSetAttribute(flash_kernel, cudaFuncAttributeMaxDynamicSharedMemorySize, FLASH_SMEM);
    cudaFuncSetAttribute(mma_tn<0>, cudaFuncAttributeMaxDynamicSharedMemorySize, GSMEM);
    cudaFuncSetAttribute(mma_tn<1>, cudaFuncAttributeMaxDynamicSharedMemorySize, GSMEM);
    cudaFuncSetAttribute(mma_tn<2>, cudaFuncAttributeMaxDynamicSharedMemorySize, GSMEM);

    const int n4 = MM * HH / 4;
    copy_kernel<<<(n4 + 255) / 256, 256>>>(hs, x, n4);

    // convert all weights to bf16 (whole tensors, 4 launches)
    const size_t W_QKV = 0, W_D = 6291456, W_1 = 8388608, W_2 = 16777216;
    cvt_kernel<<<(6291456 / 4 + 255) / 256, 256>>>(qkvw, wr + W_QKV, 6291456 / 4);
    cvt_kernel<<<(2097152 / 4 + 255) / 256, 256>>>(dw,   wr + W_D,   2097152 / 4);
    cvt_kernel<<<(8388608 / 4 + 255) / 256, 256>>>(w1,   wr + W_1,   8388608 / 4);
    cvt_kernel<<<(8388608 / 4 + 255) / 256, 256>>>(w2,   wr + W_2,   8388608 / 4);

    for (int l = 0; l < 2; ++l) {
        const __nv_bfloat16* qkvw_l = wr + W_QKV + (size_t)l * 3 * HH * HH;
        const __nv_bfloat16* dw_l   = wr + W_D   + (size_t)l * HH * HH;
        const __nv_bfloat16* w1_l   = wr + W_1   + (size_t)l * FFD * HH;
        const __nv_bfloat16* w2_l   = wr + W_2   + (size_t)l * HH * FFD;

        ln_kernel<<<MM, 256>>>(x, l1w + l * HH, l1b + l * HH, h);
        mma_tn<0><<<dim3(3 * HH / 256, MM / 128), 256, GSMEM>>>(
            h, qkvw_l, qkvb + (size_t)l * 3 * HH, nullptr, qkv, MM, 3 * HH, HH);
        flash_kernel<<<dim3(SS / 128, NHH, BB), 256, FLASH_SMEM>>>(qkv, alibi, ctx);
        mma_tn<2><<<dim3(HH / 256, MM / 128), 256, GSMEM>>>(
            ctx, dw_l, db + (size_t)l * HH, x, x, MM, HH, HH);
        ln_kernel<<<MM, 256>>>(x, l2w + l * HH, l2b + l * HH, h);
        mma_tn<1><<<dim3(FFD / 256, MM / 128), 256, GSMEM>>>(
            h, w1_l, b1 + (size_t)l * FFD, nullptr, ff, MM, FFD, HH);
        mma_tn<2><<<dim3(HH / 256, MM / 128), 256, GSMEM>>>(
            ff, w2_l, b2 + (size_t)l * HH, x, (l == 1) ? out : x, MM, HH, FFD);
    }
}

// round 16
// speedup vs baseline: 1.2013x; 1.2013x over previous
#include <cuda_runtime.h>
#include <cuda_bf16.h>
#include <math.h>
#include <stdint.h>

// ---------------- problem constants ----------------
#define BB   2
#define SS   2048
#define HH   1024
#define NHH  16
#define DHH  64
#define FFD  4096
#define MM   (BB*SS)     // 4096 rows

// ---------------- scratch (static device globals; no allocation) -----------
__device__ float          g_x  [(size_t)MM * HH];      // running residual (fp32)
__device__ __nv_bfloat16  g_h  [(size_t)MM * HH];      // layernorm output
__device__ __nv_bfloat16  g_qkv[(size_t)MM * 3 * HH];  // qkv projection
__device__ __nv_bfloat16  g_ctx[(size_t)MM * HH];      // attention context
__device__ __nv_bfloat16  g_ff [(size_t)MM * FFD];     // mlp hidden
__device__ __nv_bfloat16  g_wr [(size_t)25165824];     // bf16 weights (all)

// ---------------- small helpers ----------------
__device__ __forceinline__ float warp_sum(float v) {
#pragma unroll
    for (int o = 16; o; o >>= 1) v += __shfl_xor_sync(0xffffffffu, v, o);
    return v;
}
__device__ __forceinline__ float gelu_exact(float v) {
    return 0.5f * v * (1.0f + erff(v * 0.70710678118654752f));
}
#define MMA_BF16(d, a0, a1, a2, a3, b0, b1)                                   \
    asm volatile("mma.sync.aligned.m16n8k16.row.col.f32.bf16.bf16.f32 "       \
                 "{%0,%1,%2,%3}, {%4,%5,%6,%7}, {%8,%9}, {%0,%1,%2,%3};"      \
                 : "+f"((d)[0]), "+f"((d)[1]), "+f"((d)[2]), "+f"((d)[3])     \
                 : "r"(a0), "r"(a1), "r"(a2), "r"(a3), "r"(b0), "r"(b1))

__device__ __forceinline__ void ldsm_x4(uint32_t* r, uint32_t a) {
    asm volatile("ldmatrix.sync.aligned.m8n8.x4.shared.b16 {%0,%1,%2,%3}, [%4];"
                 : "=r"(r[0]), "=r"(r[1]), "=r"(r[2]), "=r"(r[3]) : "r"(a));
}
__device__ __forceinline__ void ldsm_x4t(uint32_t* r, uint32_t a) {
    asm volatile("ldmatrix.sync.aligned.m8n8.x4.trans.shared.b16 {%0,%1,%2,%3}, [%4];"
                 : "=r"(r[0]), "=r"(r[1]), "=r"(r[2]), "=r"(r[3]) : "r"(a));
}
#define CP16(dst, src)                                                         \
    asm volatile("cp.async.cg.shared.global [%0], [%1], 16;\n" :: "r"(dst), "l"(src))
#define CP_COMMIT() asm volatile("cp.async.commit_group;\n")
#define CP_WAIT0()  asm volatile("cp.async.wait_group 0;\n")
#define CP_WAIT1()  asm volatile("cp.async.wait_group 1;\n")

// ---------------- copy input -> g_x ----------------
__global__ void copy_kernel(const float* __restrict__ in, float* __restrict__ out, int n4) {
    int i = blockIdx.x * blockDim.x + threadIdx.x;
    if (i < n4) ((float4*)out)[i] = ((const float4*)in)[i];
}

// ---------------- fp32 -> bf16 weight conversion ----------------
__global__ void cvt_kernel(const float* __restrict__ in, __nv_bfloat16* __restrict__ out, int n4) {
    int i = blockIdx.x * blockDim.x + threadIdx.x;
    if (i < n4) {
        const float4 v = ((const float4*)in)[i];
        __nv_bfloat162 a = __floats2bfloat162_rn(v.x, v.y);
        __nv_bfloat162 b = __floats2bfloat162_rn(v.z, v.w);
        uint2 w; w.x = *(uint32_t*)&a; w.y = *(uint32_t*)&b;
        ((uint2*)out)[i] = w;
    }
}

// ---------------- layernorm: 1 block (256 thr) per row of 1024 -------------
__global__ void ln_kernel(const float* __restrict__ x, const float* __restrict__ w,
                          const float* __restrict__ b, __nv_bfloat16* __restrict__ o) {
    __shared__ float r1[8], r2[8];
    const int row = blockIdx.x, tid = threadIdx.x;
    const float4 v = *(const float4*)(x + (size_t)row * HH + tid * 4);
    float s = v.x + v.y + v.z + v.w;
    s = warp_sum(s);
    if ((tid & 31) == 0) r1[tid >> 5] = s;
    __syncthreads();
    float mean = 0.f;
#pragma unroll
    for (int i = 0; i < 8; i++) mean += r1[i];
    mean *= (1.f / (float)HH);
    const float d0 = v.x - mean, d1 = v.y - mean, d2 = v.z - mean, d3 = v.w - mean;
    float sq = d0 * d0 + d1 * d1 + d2 * d2 + d3 * d3;
    sq = warp_sum(sq);
    if ((tid & 31) == 0) r2[tid >> 5] = sq;
    __syncthreads();
    float var = 0.f;
#pragma unroll
    for (int i = 0; i < 8; i++) var += r2[i];
    var *= (1.f / (float)HH);
    const float rstd = rsqrtf(var + 1e-5f);
    const float4 wv = *(const float4*)(w + tid * 4);
    const float4 bv = *(const float4*)(b + tid * 4);
    __nv_bfloat162 o0 = __floats2bfloat162_rn(d0 * rstd * wv.x + bv.x, d1 * rstd * wv.y + bv.y);
    __nv_bfloat162 o1 = __floats2bfloat162_rn(d2 * rstd * wv.z + bv.z, d3 * rstd * wv.w + bv.w);
    uint2 pk; pk.x = *(uint32_t*)&o0; pk.y = *(uint32_t*)&o1;
    *(uint2*)(o + (size_t)row * HH + tid * 4) = pk;
}

// ---------------- bf16 tensor-core GEMM (TN) -------------------------------
// CTA tile 256x128x64, 512 thr / 16 warps (4x4), warp tile 64x32 (as R8),
// 3-stage cp.async, swizzled ldmatrix. chunk' = chunk ^ (row & 7).
#define GST    49152                 // bytes per stage (A 32KB + B 16KB)
#define GSMEM  (3*GST)               // 147456

template <int EPI>
__global__ void __launch_bounds__(512, 1) mma_tn(
        const __nv_bfloat16* __restrict__ A, const __nv_bfloat16* __restrict__ W,
        const float* __restrict__ bias, const float* __restrict__ res,
        void* __restrict__ Cout, int M, int N, int K) {
    extern __shared__ uint8_t smraw[];
    const uint32_t smbase = (uint32_t)__cvta_generic_to_shared(smraw);
    const int tid = threadIdx.x;
    const int warp = tid >> 5, lane = tid & 31;
    const int wm = warp >> 2, wn = warp & 3;      // 4 x 4 warp grid
    const int g = lane >> 2, t = lane & 3;
    const int mb = blockIdx.y << 8, nb = blockIdx.x << 7;

    // ---- staging geometry ----
    // A: 256 rows x 8 chunks, 4 chunks/thread: row = tid>>1, chunks (tid&1)*4..+3
    // B: 128 rows x 8 chunks, 2 chunks/thread: row = tid>>2, chunks (tid&3)*2..+1
    const int ra = tid >> 1, kca = (tid & 1) << 2;
    const int rb = tid >> 2, kcb = (tid & 3) << 1;
    const __nv_bfloat16* Ag = A + (size_t)(mb + ra) * K + kca * 8;
    const __nv_bfloat16* Wg = W + (size_t)(nb + rb) * K + kcb * 8;
    uint32_t offA[4], offB[2];
#pragma unroll
    for (int i = 0; i < 4; i++)
        offA[i] = ra * 128 + (((kca + i) ^ (ra & 7)) << 4);
#pragma unroll
    for (int i = 0; i < 2; i++)
        offB[i] = 32768 + rb * 128 + (((kcb + i) ^ (rb & 7)) << 4);

    // ---- fragment addresses ----
    const uint32_t la7 = lane & 7, la15 = lane & 15;
    const uint32_t hiA = lane >> 4, hiB = (lane >> 3) & 1;
    const uint32_t aRow = (wm * 64 + la15) * 128;
    const uint32_t bRow = 32768 + (wn * 32 + la7 + ((lane >> 4) << 3)) * 128;

    float acc[4][4][4];
#pragma unroll
    for (int a = 0; a < 4; a++)
#pragma unroll
        for (int b = 0; b < 4; b++)
#pragma unroll
            for (int c = 0; c < 4; c++) acc[a][b][c] = 0.f;

    const int nk = K >> 6;
    auto issue = [&](int kt, int s) {
        const __nv_bfloat16* ap = Ag + (kt << 6);
        const __nv_bfloat16* wp = Wg + (kt << 6);
        const uint32_t sb = smbase + (uint32_t)s * GST;
#pragma unroll
        for (int i = 0; i < 4; i++) CP16(sb + offA[i], ap + i * 8);
#pragma unroll
        for (int i = 0; i < 2; i++) CP16(sb + offB[i], wp + i * 8);
        CP_COMMIT();
    };

    issue(0, 0);
    issue(1, 1);

    int stage = 0;
    for (int kt = 0; kt < nk; ++kt) {
        if (kt == nk - 1) CP_WAIT0(); else CP_WAIT1();
        __syncthreads();
        if (kt + 2 < nk) {
            int ns = stage + 2; if (ns >= 3) ns -= 3;
            issue(kt + 2, ns);
        }
        const uint32_t sb = smbase + (uint32_t)stage * GST;
#pragma unroll
        for (int kk = 0; kk < 4; kk++) {
            const uint32_t swzA = (((2 * kk + hiA) ^ la7) << 4);
            const uint32_t swzB = (((2 * kk + hiB) ^ la7) << 4);
            uint32_t af[4][4], bf[2][4];
#pragma unroll
            for (int mt = 0; mt < 4; mt++)
                ldsm_x4(af[mt], sb + aRow + mt * 2048 + swzA);
#pragma unroll
            for (int p = 0; p < 2; p++)
                ldsm_x4(bf[p], sb + bRow + p * 2048 + swzB);
#pragma unroll
            for (int mt = 0; mt < 4; mt++)
#pragma unroll
                for (int nt = 0; nt < 4; nt++)
                    MMA_BF16(acc[mt][nt], af[mt][0], af[mt][1], af[mt][2], af[mt][3],
                             bf[nt >> 1][(nt & 1) * 2], bf[nt >> 1][(nt & 1) * 2 + 1]);
        }
        if (++stage == 3) stage = 0;
    }

    // epilogue: c0,c1 -> (row g, cols 2t,2t+1); c2,c3 -> (row g+8)
#pragma unroll
    for (int mt = 0; mt < 4; mt++) {
        const int r0 = mb + wm * 64 + mt * 16 + g;
#pragma unroll
        for (int nt = 0; nt < 4; nt++) {
            const int cb = nb + wn * 32 + nt * 8 + 2 * t;
            const float b0 = bias[cb], b1 = bias[cb + 1];
#pragma unroll
            for (int hh = 0; hh < 2; hh++) {
                const int rr = r0 + hh * 8;
                float v0 = acc[mt][nt][2 * hh + 0] + b0;
                float v1 = acc[mt][nt][2 * hh + 1] + b1;
                const size_t off = (size_t)rr * N + cb;
                if (EPI == 2) {
                    const float2 rv = *(const float2*)(res + off);
                    *(float2*)((float*)Cout + off) = make_float2(v0 + rv.x, v1 + rv.y);
                } else {
                    if (EPI == 1) { v0 = gelu_exact(v0); v1 = gelu_exact(v1); }
                    __nv_bfloat162 h2 = __floats2bfloat162_rn(v0, v1);
                    *(uint32_t*)((__nv_bfloat16*)Cout + off) = *(uint32_t*)&h2;
                }
            }
        }
    }
}

// ---------------- bf16 tensor-core flash attention (causal, ALiBi) ---------
// grid: (S/128, NH, B), 256 thr (8 warps x 16 q-rows). P kept in registers.
// Heaviest q-tiles scheduled first (qt descending in launch order).
#define FSTG 16640
#define FLASH_SMEM (16384 + 3*FSTG)
__global__ void __launch_bounds__(256, 2) flash_kernel(
        const __nv_bfloat16* __restrict__ qkv, const float* __restrict__ alibi,
        __nv_bfloat16* __restrict__ ctx) {
    extern __shared__ uint8_t smraw[];
    const uint32_t smbase = (uint32_t)__cvta_generic_to_shared(smraw);
    uint32_t* smw = (uint32_t*)smraw;

    const int qt = gridDim.x - 1 - blockIdx.x;   // big blocks first
    const int hh = blockIdx.y, bb = blockIdx.z;
    const int tid = threadIdx.x;
    const int warp = tid >> 5, lane = tid & 31;
    const int g = lane >> 2, t = lane & 3;
    const int qbase = qt << 7;

    const __nv_bfloat16* qg  = qkv + (size_t)bb * SS * (3 * HH) + hh * DHH;
    const __nv_bfloat16* kg  = qg + HH;
    const __nv_bfloat16* vg  = qg + 2 * HH;
    const float* alg = alibi + ((size_t)bb * NHH + hh) * SS;

    const int lrow = (tid & 127) >> 1, lkc = (tid & 1) << 2;
    const __nv_bfloat16* kvsrc = ((tid >= 128) ? vg : kg) + (size_t)lrow * (3 * HH) + lkc * 8;
    uint32_t offKV[4];
#pragma unroll
    for (int i = 0; i < 4; i++)
        offKV[i] = ((tid >= 128) ? 8192u : 0u) + lrow * 128 + (((lkc + i) ^ (lrow & 7)) << 4);

    auto issue = [&](int jt, int s) {
        const uint32_t sb = smbase + 16384 + (uint32_t)s * FSTG;
        const __nv_bfloat16* src = kvsrc + (size_t)(jt << 6) * (3 * HH);
#pragma unroll
        for (int i = 0; i < 4; i++) CP16(sb + offKV[i], src + i * 8);
        if (tid < 16) CP16(sb + 16384 + tid * 16, alg + (jt << 6) + tid * 4);
        CP_COMMIT();
    };

    for (int f = tid; f < 1024; f += 256) {
        const int r = f >> 3, c = f & 7;
        const uint4 q4 = *(const uint4*)(qg + (size_t)(qbase + r) * (3 * HH) + c * 8);
        *(uint4*)(smw + r * 32 + ((c ^ (r & 7)) << 2)) = q4;
    }
    const int njt = 2 * qt + 2;
    issue(0, 0);
    issue(1, 1);
    __syncthreads();

    const uint32_t la7 = lane & 7, la15 = lane & 15;
    const uint32_t hiA = lane >> 4, hiB = (lane >> 3) & 1;
    const uint32_t qAddr = smbase + (warp * 16 + la15) * 128;
    uint32_t qf[4][4];
#pragma unroll
    for (int kk = 0; kk < 4; kk++)
        ldsm_x4(qf[kk], qAddr + (((2 * kk + hiA) ^ la7) << 4));

    const uint32_t kRow = (la7 + ((lane >> 4) << 3)) * 128;
    const uint32_t vKey = (la7 + (hiB << 3)) * 128;

    float mx[2] = { -INFINITY, -INFINITY };
    float lsum[2] = { 0.f, 0.f };
    float acc[8][4];
#pragma unroll
    for (int nt = 0; nt < 8; nt++)
#pragma unroll
        for (int c = 0; c < 4; c++) acc[nt][c] = 0.f;

    int stage = 0;
    for (int jt = 0; jt < njt; ++jt) {
        const int kbase = jt << 6;
        if (jt == njt - 1) CP_WAIT0(); else CP_WAIT1();
        __syncthreads();
        if (jt + 2 < njt) {
            int ns = stage + 2; if (ns >= 3) ns -= 3;
            issue(jt + 2, ns);
        }
        const uint32_t sK = smbase + 16384 + (uint32_t)stage * FSTG;
        const uint32_t sV = sK + 8192;
        const float* alS = (const float*)(smraw + 16384 + (size_t)stage * FSTG + 16384);

        float s[8][4];
#pragma unroll
        for (int nt = 0; nt < 8; nt++)
#pragma unroll
            for (int c = 0; c < 4; c++) s[nt][c] = 0.f;
#pragma unroll
        for (int kk = 0; kk < 4; ++kk) {
            const uint32_t swzB = (((2 * kk + hiB) ^ la7) << 4);
            uint32_t kf[4][4];
#pragma unroll
            for (int p = 0; p < 4; p++)
                ldsm_x4(kf[p], sK + kRow + p * 2048 + swzB);
#pragma unroll
            for (int nt = 0; nt < 8; ++nt)
                MMA_BF16(s[nt], qf[kk][0], qf[kk][1], qf[kk][2], qf[kk][3],
                         kf[nt >> 1][(nt & 1) * 2], kf[nt >> 1][(nt & 1) * 2 + 1]);
        }

        const bool need_mask = (jt >= 2 * qt);
        uint32_t pr[8][2];
#pragma unroll
        for (int r = 0; r < 2; ++r) {
            const int qr = qbase + warp * 16 + g + r * 8;
            float rowmax = -INFINITY;
#pragma unroll
            for (int nt = 0; nt < 8; ++nt) {
#pragma unroll
                for (int c = 0; c < 2; ++c) {
                    const int col = nt * 8 + 2 * t + c;
                    float v = s[nt][r * 2 + c] * 0.125f + alS[col];
                    if (need_mask && (kbase + col > qr)) v = -1e30f;
                    s[nt][r * 2 + c] = v;
                    rowmax = fmaxf(rowmax, v);
                }
            }
            rowmax = fmaxf(rowmax, __shfl_xor_sync(0xffffffffu, rowmax, 1));
            rowmax = fmaxf(rowmax, __shfl_xor_sync(0xffffffffu, rowmax, 2));
            const float mn = fmaxf(mx[r], rowmax);
            const float corr = __expf(mx[r] - mn);
            mx[r] = mn;
            float rs = 0.f;
#pragma unroll
            for (int nt = 0; nt < 8; ++nt) {
                const float p0 = __expf(s[nt][r * 2 + 0] - mn);
                const float p1 = __expf(s[nt][r * 2 + 1] - mn);
                const __nv_bfloat162 h2 = __floats2bfloat162_rn(p0, p1);
                rs += __bfloat162float(h2.x) + __bfloat162float(h2.y);
                pr[nt][r] = *(const uint32_t*)&h2;
            }
            rs += __shfl_xor_sync(0xffffffffu, rs, 1);
            rs += __shfl_xor_sync(0xffffffffu, rs, 2);
            lsum[r] = lsum[r] * corr + rs;
#pragma unroll
            for (int nt = 0; nt < 8; ++nt) {
                acc[nt][r * 2 + 0] *= corr;
                acc[nt][r * 2 + 1] *= corr;
            }
        }

#pragma unroll
        for (int kk = 0; kk < 4; ++kk) {
            const uint32_t a0 = pr[2 * kk][0],     a1 = pr[2 * kk][1];
            const uint32_t a2 = pr[2 * kk + 1][0], a3 = pr[2 * kk + 1][1];
            const uint32_t vBase = sV + vKey + kk * 2048;
            uint32_t vf[4][4];
#pragma unroll
            for (int p = 0; p < 4; p++) {
                const uint32_t chunk = 2 * p + hiA;
                ldsm_x4t(vf[p], vBase + ((chunk ^ la7) << 4));
            }
#pragma unroll
            for (int nt = 0; nt < 8; ++nt)
                MMA_BF16(acc[nt], a0, a1, a2, a3,
                         vf[nt >> 1][(nt & 1) * 2], vf[nt >> 1][(nt & 1) * 2 + 1]);
        }
        if (++stage == 3) stage = 0;
    }

    const float inv0 = 1.f / lsum[0], inv1 = 1.f / lsum[1];
    const int r0 = qbase + warp * 16 + g;
    __nv_bfloat16* o0 = ctx + ((size_t)bb * SS + r0) * HH + hh * DHH;
    __nv_bfloat16* o1 = o0 + (size_t)8 * HH;
#pragma unroll
    for (int nt = 0; nt < 8; ++nt) {
        const int col = nt * 8 + 2 * t;
        __nv_bfloat162 w0 = __floats2bfloat162_rn(acc[nt][0] * inv0, acc[nt][1] * inv0);
        __nv_bfloat162 w1 = __floats2bfloat162_rn(acc[nt][2] * inv1, acc[nt][3] * inv1);
        *(uint32_t*)(o0 + col) = *(uint32_t*)&w0;
        *(uint32_t*)(o1 + col) = *(uint32_t*)&w1;
    }
}

// ---------------- driver ----------------
extern "C" void kernel_launch(void* const* d_in, const int* in_sizes, int n_in,
                              void* d_out, int out_size) {
    const float* hs    = (const float*)d_in[0];
    const float* alibi = (const float*)d_in[1];
    const float* qkvw  = (const float*)d_in[2];
    const float* qkvb  = (const float*)d_in[3];
    const float* dw    = (const float*)d_in[4];
    const float* db    = (const float*)d_in[5];
    const float* w1    = (const float*)d_in[6];
    const float* b1    = (const float*)d_in[7];
    const float* w2    = (const float*)d_in[8];
    const float* b2    = (const float*)d_in[9];
    const float* l1w   = (const float*)d_in[10];
    const float* l1b   = (const float*)d_in[11];
    const float* l2w   = (const float*)d_in[12];
    const float* l2b   = (const float*)d_in[13];
    float* out = (float*)d_out;

    float *x;
    __nv_bfloat16 *h, *qkv, *ctx, *ff, *wr;
    cudaGetSymbolAddress((void**)&x,   g_x);
    cudaGetSymbolAddress((void**)&h,   g_h);
    cudaGetSymbolAddress((void**)&qkv, g_qkv);
    cudaGetSymbolAddress((void**)&ctx, g_ctx);
    cudaGetSymbolAddress((void**)&ff,  g_ff);
    cudaGetSymbolAddress((void**)&wr,  g_wr);

    cudaFuncSetAttribute(flash_kernel, cudaFuncAttributeMaxDynamicSharedMemorySize, FLASH_SMEM);
    cudaFuncSetAttribute(mma_tn<0>, cudaFuncAttributeMaxDynamicSharedMemorySize, GSMEM);
    cudaFuncSetAttribute(mma_tn<1>, cudaFuncAttributeMaxDynamicSharedMemorySize, GSMEM);
    cudaFuncSetAttribute(mma_tn<2>, cudaFuncAttributeMaxDynamicSharedMemorySize, GSMEM);

    const int n4 = MM * HH / 4;
    copy_kernel<<<(n4 + 255) / 256, 256>>>(hs, x, n4);

    // convert all weights to bf16 (whole tensors, 4 launches)
    const size_t W_QKV = 0, W_D = 6291456, W_1 = 8388608, W_2 = 16777216;
    cvt_kernel<<<(6291456 / 4 + 255) / 256, 256>>>(qkvw, wr + W_QKV, 6291456 / 4);
    cvt_kernel<<<(2097152 / 4 + 255) / 256, 256>>>(dw,   wr + W_D,   2097152 / 4);
    cvt_kernel<<<(8388608 / 4 + 255) / 256, 256>>>(w1,   wr + W_1,   8388608 / 4);
    cvt_kernel<<<(8388608 / 4 + 255) / 256, 256>>>(w2,   wr + W_2,   8388608 / 4);

    for (int l = 0; l < 2; ++l) {
        const __nv_bfloat16* qkvw_l = wr + W_QKV + (size_t)l * 3 * HH * HH;
        const __nv_bfloat16* dw_l   = wr + W_D   + (size_t)l * HH * HH;
        const __nv_bfloat16* w1_l   = wr + W_1   + (size_t)l * FFD * HH;
        const __nv_bfloat16* w2_l   = wr + W_2   + (size_t)l * HH * FFD;

        ln_kernel<<<MM, 256>>>(x, l1w + l * HH, l1b + l * HH, h);
        mma_tn<0><<<dim3(3 * HH / 128, MM / 256), 512, GSMEM>>>(
            h, qkvw_l, qkvb + (size_t)l * 3 * HH, nullptr, qkv, MM, 3 * HH, HH);
        flash_kernel<<<dim3(SS / 128, NHH, BB), 256, FLASH_SMEM>>>(qkv, alibi, ctx);
        mma_tn<2><<<dim3(HH / 128, MM / 256), 512, GSMEM>>>(
            ctx, dw_l, db + (size_t)l * HH, x, x, MM, HH, HH);
        ln_kernel<<<MM, 256>>>(x, l2w + l * HH, l2b + l * HH, h);
        mma_tn<1><<<dim3(FFD / 128, MM / 256), 512, GSMEM>>>(
            h, w1_l, b1 + (size_t)l * FFD, nullptr, ff, MM, FFD, HH);
        mma_tn<2><<<dim3(HH / 128, MM / 256), 512, GSMEM>>>(
            ff, w2_l, b2 + (size_t)l * HH, x, (l == 1) ? out : x, MM, HH, FFD);
    }
}